// round 16
// baseline (speedup 1.0000x reference)
#include <cuda_runtime.h>
#include <cuda_bf16.h>

// MultiPrototypeLoss — persistent block-per-row, PAIR-grained dynamic rows
// + 32KB bulk L2 prefetch (pre-barrier) + base-2 softmin.
// B=16384 (even), C=1000, P=4; 262MB once-read stream (HBM-bound).
// d[b,c] = -logsumexp(-x[b,4c..4c+3]); loss = mean_b (d[b,l]/out_mean)^2.
//
// vs R15 (41.2us): rows claimed in contiguous PAIRS (one atomic, one 32KB
// cp.async.bulk.prefetch.L2 per 2 rows), prefetch issued pre-barrier to
// de-burst DRAM demand. Consuming LDG.128s hit L2 (~240cyc), fully covered
// by the batched register prefetch. First pair static (no prologue storm).
// Labels: runtime int32/int64 detection (JAX x64 ambiguity).

#define NUM_C     1000
#define ROW_BYTES (NUM_C * 16)
#define THREADS   256
#define WARPS     (THREADS / 32)
#define GRID      (148 * 8)

#define L2E  1.4426950408889634f   // log2(e)
#define LN2  0.6931471805599453f

__device__ double   g_acc   = 0.0;
__device__ unsigned g_count = 0u;
__device__ unsigned g_row   = 2u * GRID;   // next unclaimed PAIR base (even)

__device__ __forceinline__ void l2_prefetch_pair(const char* p) {
    asm volatile("cp.async.bulk.prefetch.L2.global [%0], %1;"
                 :: "l"(p), "r"(2 * ROW_BYTES) : "memory");
}

__device__ __forceinline__ void group_ms(float4 v, float& m, float& s) {
    m = fminf(fminf(v.x, v.y), fminf(v.z, v.w));
    float mL = m * L2E;
    s = (exp2f(fmaf(v.x, -L2E, mL)) + exp2f(fmaf(v.y, -L2E, mL))) +
        (exp2f(fmaf(v.z, -L2E, mL)) + exp2f(fmaf(v.w, -L2E, mL)));
}

__global__ __launch_bounds__(THREADS, 8) void mpl_kernel(
    const float4* __restrict__ dist,       // [B, NUM_C] float4 groups
    const int*    __restrict__ labels_raw, // [B] int32 OR int64 (as words)
    float*        __restrict__ out,
    int B)
{
    const int tid = threadIdx.x;
    const int lid = tid & 31;
    const int wid = tid >> 5;

    __shared__ int   s_pair[2];            // grabbed pair bases (alternating)
    __shared__ float s_sum[2][WARPS];
    __shared__ float s_in_m[2];
    __shared__ float s_in_s[2];

    // prologue: grab pair1 (pair0 = 2*blockIdx.x is static)
    if (tid == 0) s_pair[0] = (int)atomicAdd(&g_row, 2u);

    // --- inline label-dtype detection; barrier publishes s_pair[0] too ---
    int odd_idx = 2 * tid + 1;
    int nz = (odd_idx < B) ? (labels_raw[odd_idx] != 0) : 0;
    const int labels_are_i32 = __syncthreads_or(nz);

    const int c0 = tid;
    const int c1 = tid + THREADS;
    const int c2 = tid + 2 * THREADS;
    const int c3 = tid + 3 * THREADS;
    const bool has3 = (c3 < NUM_C);          // tid < 232

    double local_acc = 0.0;                  // meaningful on tid 0

    int rowA  = 2 * blockIdx.x;              // current pair base (even, < B)
    int pNext = s_pair[0];                   // next pair base
    int pq    = 1;                           // s_pair slot for next grab

    // prologue: L2-prefetch pair1; load rowA into v regs
    if (tid == 0 && pNext < B)
        l2_prefetch_pair((const char*)dist + (size_t)pNext * ROW_BYTES);
    float4 v0, v1, v2, v3;
    int lbl;
    {
        const float4* rp = dist + (size_t)rowA * NUM_C;
        lbl = labels_are_i32 ? labels_raw[rowA] : labels_raw[2 * rowA];
        v0 = __ldcs(rp + c0);
        v1 = __ldcs(rp + c1);
        v2 = __ldcs(rp + c2);
        if (has3) v3 = __ldcs(rp + c3);
    }

    while (rowA < B) {
        const int rowB = rowA + 1;           // rowA even, B even -> rowB < B

        // ================= iteration A (parity slot 0) =================
        {
            const int cur_lbl = lbl;
            float mm, sp;
            { float m,s; group_ms(v0,m,s); if (c0==cur_lbl){s_in_m[0]=m;s_in_s[0]=s;} mm=m;  sp=s;  }
            { float m,s; group_ms(v1,m,s); if (c1==cur_lbl){s_in_m[0]=m;s_in_s[0]=s;} mm+=m; sp*=s; }
            { float m,s; group_ms(v2,m,s); if (c2==cur_lbl){s_in_m[0]=m;s_in_s[0]=s;} mm+=m; sp*=s; }
            if (has3)
            { float m,s; group_ms(v3,m,s); if (c3==cur_lbl){s_in_m[0]=m;s_in_s[0]=s;} mm+=m; sp*=s; }

            // batched v-reg prefetch of rowB (always valid)
            {
                const float4* rp = dist + (size_t)rowB * NUM_C;
                lbl = labels_are_i32 ? labels_raw[rowB] : labels_raw[2 * rowB];
                v0 = __ldcs(rp + c0);
                v1 = __ldcs(rp + c1);
                v2 = __ldcs(rp + c2);
                if (has3) v3 = __ldcs(rp + c3);
            }

            // grab pair k+2 and L2-prefetch it NOW (pre-barrier, de-bursted)
            if (tid == 0) {
                int p = (int)atomicAdd(&g_row, 2u);
                s_pair[pq] = p;
                if (p < B)
                    l2_prefetch_pair((const char*)dist + (size_t)p * ROW_BYTES);
            }

            float sum_d = fmaf(-LN2, __log2f(sp), mm);
#pragma unroll
            for (int off = 16; off > 0; off >>= 1)
                sum_d += __shfl_xor_sync(0xFFFFFFFFu, sum_d, off);
            if (lid == 0) s_sum[0][wid] = sum_d;

            __syncthreads();                 // barrier A

            if (tid == 0) {
                float tot = 0.0f;
#pragma unroll
                for (int w = 0; w < WARPS; w++) tot += s_sum[0][w];
                float inc = fmaf(-LN2, __log2f(s_in_s[0]), s_in_m[0]);
                float om = (tot - inc) * (1.0f / (NUM_C - 1));
                float r = inc / om;
                local_acc += (double)(r * r);
            }
        }

        const int pN2 = s_pair[pq];          // pair k+2 (visible post-bar A)

        // ================= iteration B (parity slot 1) =================
        {
            const int cur_lbl = lbl;
            float mm, sp;
            { float m,s; group_ms(v0,m,s); if (c0==cur_lbl){s_in_m[1]=m;s_in_s[1]=s;} mm=m;  sp=s;  }
            { float m,s; group_ms(v1,m,s); if (c1==cur_lbl){s_in_m[1]=m;s_in_s[1]=s;} mm+=m; sp*=s; }
            { float m,s; group_ms(v2,m,s); if (c2==cur_lbl){s_in_m[1]=m;s_in_s[1]=s;} mm+=m; sp*=s; }
            if (has3)
            { float m,s; group_ms(v3,m,s); if (c3==cur_lbl){s_in_m[1]=m;s_in_s[1]=s;} mm+=m; sp*=s; }

            // batched v-reg prefetch of pair k+1's first row
            if (pNext < B) {
                const float4* rp = dist + (size_t)pNext * NUM_C;
                lbl = labels_are_i32 ? labels_raw[pNext] : labels_raw[2 * pNext];
                v0 = __ldcs(rp + c0);
                v1 = __ldcs(rp + c1);
                v2 = __ldcs(rp + c2);
                if (has3) v3 = __ldcs(rp + c3);
            }

            float sum_d = fmaf(-LN2, __log2f(sp), mm);
#pragma unroll
            for (int off = 16; off > 0; off >>= 1)
                sum_d += __shfl_xor_sync(0xFFFFFFFFu, sum_d, off);
            if (lid == 0) s_sum[1][wid] = sum_d;

            __syncthreads();                 // barrier B

            if (tid == 0) {
                float tot = 0.0f;
#pragma unroll
                for (int w = 0; w < WARPS; w++) tot += s_sum[1][w];
                float inc = fmaf(-LN2, __log2f(s_in_s[1]), s_in_m[1]);
                float om = (tot - inc) * (1.0f / (NUM_C - 1));
                float r = inc / om;
                local_acc += (double)(r * r);
            }
        }

        rowA  = pNext;
        pNext = pN2;
        pq   ^= 1;
    }

    if (tid == 0) {
        atomicAdd(&g_acc, local_acc);
        __threadfence();
        unsigned t = atomicAdd(&g_count, 1u);
        if (t == gridDim.x - 1) {            // last block: finalize + reset
            double a = atomicAdd(&g_acc, 0.0);
            *out = (float)(a / (double)B);
            g_acc   = 0.0;                   // restore invariants for replay
            g_count = 0u;
            g_row   = 2u * GRID;
        }
    }
}

extern "C" void kernel_launch(void* const* d_in, const int* in_sizes, int n_in,
                              void* d_out, int out_size) {
    const float4* dist   = (const float4*)d_in[0];
    const int*    labels = (const int*)d_in[1];
    float*        out    = (float*)d_out;
    const int B = in_sizes[1];   // label element count == batch size

    mpl_kernel<<<GRID, THREADS>>>(dist, labels, out, B);
}

// round 17
// speedup vs baseline: 1.0104x; 1.0104x over previous
#include <cuda_runtime.h>
#include <cuda_bf16.h>

// MultiPrototypeLoss — persistent block-per-row, dynamic rows, 3-row window
// + bulk L2 prefetch with ~2.5-row lead + base-2 softmin.  (R15 + depth)
// B=16384, C=1000, P=4; 262MB once-read stream (HBM-bound).
// d[b,c] = -logsumexp(-x[b,4c..4c+3]); loss = mean_b (d[b,l]/out_mean)^2.
//
// R15 (41.2us): L2 prefetch of r_{i+2} issued post-barrier, ~1.5-row lead.
// Here the window is (r_i, r_{i+1}, r_{i+2}); tid0 grabs r_{i+3} and issues
// its 16KB cp.async.bulk.prefetch.L2 IMMEDIATELY (pre-barrier): ~2.5-row
// lead, prefetch issue decoupled from the barrier instant. Loop body,
// v-reg prefetch, reduce, and epilogue are unchanged from R15.
// Labels: runtime int32/int64 detection (JAX x64 ambiguity).

#define NUM_C     1000
#define ROW_BYTES (NUM_C * 16)
#define THREADS   256
#define WARPS     (THREADS / 32)
#define GRID      (148 * 8)

#define L2E  1.4426950408889634f   // log2(e)
#define LN2  0.6931471805599453f

__device__ double   g_acc   = 0.0;
__device__ unsigned g_count = 0u;
__device__ unsigned g_row   = GRID;   // next unclaimed row

__device__ __forceinline__ void l2_prefetch_row(const char* p) {
    asm volatile("cp.async.bulk.prefetch.L2.global [%0], %1;"
                 :: "l"(p), "r"(ROW_BYTES) : "memory");
}

__device__ __forceinline__ void group_ms(float4 v, float& m, float& s) {
    m = fminf(fminf(v.x, v.y), fminf(v.z, v.w));
    float mL = m * L2E;
    s = (exp2f(fmaf(v.x, -L2E, mL)) + exp2f(fmaf(v.y, -L2E, mL))) +
        (exp2f(fmaf(v.z, -L2E, mL)) + exp2f(fmaf(v.w, -L2E, mL)));
}

__global__ __launch_bounds__(THREADS, 8) void mpl_kernel(
    const float4* __restrict__ dist,       // [B, NUM_C] float4 groups
    const int*    __restrict__ labels_raw, // [B] int32 OR int64 (as words)
    float*        __restrict__ out,
    int B)
{
    const int tid = threadIdx.x;
    const int lid = tid & 31;
    const int wid = tid >> 5;

    __shared__ int   s_grab[2];            // newly grabbed row (alternating)
    __shared__ float s_sum[2][WARPS];
    __shared__ float s_in_m[2];
    __shared__ float s_in_s[2];

    // prologue: grab r1, r2 (r0 = blockIdx.x static); prefetch them
    if (tid == 0) {
        int r1 = (int)atomicAdd(&g_row, 1u);
        int r2 = (int)atomicAdd(&g_row, 1u);
        s_grab[0] = r1;
        s_grab[1] = r2;
        if (r1 < B) l2_prefetch_row((const char*)dist + (size_t)r1 * ROW_BYTES);
        if (r2 < B) l2_prefetch_row((const char*)dist + (size_t)r2 * ROW_BYTES);
    }

    // --- inline label-dtype detection; barrier publishes s_grab too ---
    int odd_idx = 2 * tid + 1;
    int nz = (odd_idx < B) ? (labels_raw[odd_idx] != 0) : 0;
    const int labels_are_i32 = __syncthreads_or(nz);

    const int c0 = tid;
    const int c1 = tid + THREADS;
    const int c2 = tid + 2 * THREADS;
    const int c3 = tid + 3 * THREADS;
    const bool has3 = (c3 < NUM_C);          // tid < 232

    double local_acc = 0.0;                  // meaningful on tid 0
    int par = 0;

    int row = blockIdx.x;                    // r_i
    int rn1 = s_grab[0];                     // r_{i+1}
    int rn2 = s_grab[1];                     // r_{i+2}

    // ---- prologue: load first row ----
    float4 v0, v1, v2, v3;
    int lbl = 0;
    if (row < B) {
        const float4* rowp = dist + (size_t)row * NUM_C;
        lbl = labels_are_i32 ? labels_raw[row] : labels_raw[2 * row];
        v0 = __ldcs(rowp + c0);
        v1 = __ldcs(rowp + c1);
        v2 = __ldcs(rowp + c2);
        if (has3) v3 = __ldcs(rowp + c3);
    }

    while (row < B) {
        const int cur_lbl = lbl;

        // ---- per-group softmin pieces (base-2, folded logs) ----
        float mm, sp;
        {
            float m, s; group_ms(v0, m, s);
            if (c0 == cur_lbl) { s_in_m[par] = m; s_in_s[par] = s; }
            mm = m; sp = s;
        }
        {
            float m, s; group_ms(v1, m, s);
            if (c1 == cur_lbl) { s_in_m[par] = m; s_in_s[par] = s; }
            mm += m; sp *= s;
        }
        {
            float m, s; group_ms(v2, m, s);
            if (c2 == cur_lbl) { s_in_m[par] = m; s_in_s[par] = s; }
            mm += m; sp *= s;
        }
        if (has3) {
            float m, s; group_ms(v3, m, s);
            if (c3 == cur_lbl) { s_in_m[par] = m; s_in_s[par] = s; }
            mm += m; sp *= s;
        }

        // ---- batched prefetch of r_{i+1} into freed v regs (pre-barrier) ----
        if (rn1 < B) {
            const float4* nrowp = dist + (size_t)rn1 * NUM_C;
            lbl = labels_are_i32 ? labels_raw[rn1] : labels_raw[2 * rn1];
            v0 = __ldcs(nrowp + c0);
            v1 = __ldcs(nrowp + c1);
            v2 = __ldcs(nrowp + c2);
            if (has3) v3 = __ldcs(nrowp + c3);
        }

        // ---- grab r_{i+3}; L2-prefetch it IMMEDIATELY (~2.5-row lead) ----
        if (tid == 0) {
            int rg = (int)atomicAdd(&g_row, 1u);
            s_grab[par] = rg;
            if (rg < B)
                l2_prefetch_row((const char*)dist + (size_t)rg * ROW_BYTES);
        }

        // ---- epilogue for current row ----
        float sum_d = fmaf(-LN2, __log2f(sp), mm);
#pragma unroll
        for (int off = 16; off > 0; off >>= 1)
            sum_d += __shfl_xor_sync(0xFFFFFFFFu, sum_d, off);
        if (lid == 0) s_sum[par][wid] = sum_d;

        __syncthreads();   // single barrier per row (parity protects reuse)

        if (tid == 0) {
            float tot = 0.0f;
#pragma unroll
            for (int w = 0; w < WARPS; w++) tot += s_sum[par][w];
            float inc = fmaf(-LN2, __log2f(s_in_s[par]), s_in_m[par]);
            float out_mean = (tot - inc) * (1.0f / (NUM_C - 1));
            float r = inc / out_mean;
            local_acc += (double)(r * r);
        }

        // shift 3-row window
        row = rn1;
        rn1 = rn2;
        rn2 = s_grab[par];      // r_{i+3}, visible post-barrier
        par ^= 1;
    }

    if (tid == 0) {
        atomicAdd(&g_acc, local_acc);
        __threadfence();
        unsigned t = atomicAdd(&g_count, 1u);
        if (t == gridDim.x - 1) {          // last block: finalize + reset
            double a = atomicAdd(&g_acc, 0.0);
            *out = (float)(a / (double)B);
            g_acc   = 0.0;                 // restore invariants for replay
            g_count = 0u;
            g_row   = GRID;
        }
    }
}

extern "C" void kernel_launch(void* const* d_in, const int* in_sizes, int n_in,
                              void* d_out, int out_size) {
    const float4* dist   = (const float4*)d_in[0];
    const int*    labels = (const int*)d_in[1];
    float*        out    = (float*)d_out;
    const int B = in_sizes[1];   // label element count == batch size

    mpl_kernel<<<GRID, THREADS>>>(dist, labels, out, B);
}